// round 1
// baseline (speedup 1.0000x reference)
#include <cuda_runtime.h>
#include <cmath>

#define LPN 4096
#define LHN 4096
#define DN  300
#define HN  512

// ---------------- scratch (static device globals; no runtime allocation) ----
__device__ float g_pemb[LPN * DN];
__device__ float g_hemb[LHN * DN];
__device__ float g_t   [LPN * HN];
__device__ float g_fp  [LPN * HN];
__device__ float g_fh  [LHN * HN];
__device__ float g_x   [LPN * 2 * DN];
__device__ float g_u   [LPN * HN];
__device__ float g_eik [LPN];
__device__ float g_ekj [LHN];
__device__ float g_part[32 * 4096];

// ---------------- gather: out[r,:] = emb[idx[r],:] ---------------------------
__global__ void gather_kernel(const float* __restrict__ emb,
                              const int* __restrict__ idx,
                              float* __restrict__ out, int d) {
    int r = blockIdx.x;
    long src = idx[r];
    const float* s = emb + src * (long)d;
    float* o = out + (long)r * d;
    for (int c = threadIdx.x; c < d; c += blockDim.x) o[c] = s[c];
}

// ---------------- generic tiled SGEMM ---------------------------------------
// C[m,n] = epi( sum_k A[m*sAm + k*sAk] * B[k*sBk + n*sBn] )
// epi: +bias[n] (opt), relu (opt), /rowdiv[m] (opt)
// A_MFAST: loads coalesce along m (for k-strided A), else along k.
// B_NFAST: loads coalesce along n, else along k.
template <bool A_MFAST, bool B_NFAST>
__global__ void gemm_kernel(const float* __restrict__ A, long sAm, long sAk,
                            const float* __restrict__ B, long sBk, long sBn,
                            const float* __restrict__ bias,
                            const float* __restrict__ rowdiv,
                            float* __restrict__ C, int ldc,
                            int M, int N, int K, int relu) {
    const int BM = 64, BN = 64, BK = 16;
    __shared__ float As[BK][BM + 4];
    __shared__ float Bs[BK][BN + 4];

    int tid = threadIdx.x;               // 256 threads
    int m0 = blockIdx.y * BM;
    int n0 = blockIdx.x * BN;
    int ty = tid >> 4;                    // 0..15 (m micro-tile)
    int tx = tid & 15;                    // 0..15 (n micro-tile)

    float acc[4][4];
    #pragma unroll
    for (int i = 0; i < 4; i++)
        #pragma unroll
        for (int j = 0; j < 4; j++) acc[i][j] = 0.f;

    for (int k0 = 0; k0 < K; k0 += BK) {
        // ---- load A tile (BM x BK) ----
        if (!A_MFAST) {
            int kk = tid & 15, mm = tid >> 4;
            #pragma unroll
            for (int r = 0; r < 4; r++) {
                int mr = mm + r * 16;
                int m = m0 + mr;
                As[kk][mr] = (m < M && (k0 + kk) < K)
                           ? A[(long)m * sAm + (long)(k0 + kk) * sAk] : 0.f;
            }
        } else {
            int mm = tid & 63, kb = tid >> 6;
            int m = m0 + mm;
            #pragma unroll
            for (int r = 0; r < 4; r++) {
                int kk = kb + r * 4;
                As[kk][mm] = (m < M && (k0 + kk) < K)
                           ? A[(long)m * sAm + (long)(k0 + kk) * sAk] : 0.f;
            }
        }
        // ---- load B tile (BK x BN) ----
        if (B_NFAST) {
            int nn = tid & 63, kb = tid >> 6;
            int n = n0 + nn;
            #pragma unroll
            for (int r = 0; r < 4; r++) {
                int kk = kb + r * 4;
                Bs[kk][nn] = (n < N && (k0 + kk) < K)
                           ? B[(long)(k0 + kk) * sBk + (long)n * sBn] : 0.f;
            }
        } else {
            int kk = tid & 15, nb = tid >> 4;
            #pragma unroll
            for (int r = 0; r < 4; r++) {
                int nr = nb + r * 16;
                int n = n0 + nr;
                Bs[kk][nr] = (n < N && (k0 + kk) < K)
                           ? B[(long)(k0 + kk) * sBk + (long)n * sBn] : 0.f;
            }
        }
        __syncthreads();

        #pragma unroll
        for (int kk = 0; kk < BK; kk++) {
            float a[4], b[4];
            #pragma unroll
            for (int i = 0; i < 4; i++) a[i] = As[kk][ty * 4 + i];
            #pragma unroll
            for (int j = 0; j < 4; j++) b[j] = Bs[kk][tx * 4 + j];
            #pragma unroll
            for (int i = 0; i < 4; i++)
                #pragma unroll
                for (int j = 0; j < 4; j++) acc[i][j] += a[i] * b[j];
        }
        __syncthreads();
    }

    #pragma unroll
    for (int i = 0; i < 4; i++) {
        int m = m0 + ty * 4 + i;
        if (m >= M) continue;
        float rd = rowdiv ? rowdiv[m] : 1.f;
        #pragma unroll
        for (int j = 0; j < 4; j++) {
            int n = n0 + tx * 4 + j;
            if (n >= N) continue;
            float v = acc[i][j];
            if (bias) v += bias[n];
            if (relu) v = fmaxf(v, 0.f);
            if (rowdiv) v /= rd;
            C[(long)m * ldc + n] = v;
        }
    }
}

// ---------------- row sums: out[r] = sum_c A[r,c] ---------------------------
__global__ void rowsum_kernel(const float* __restrict__ A,
                              float* __restrict__ out, int cols) {
    __shared__ float sm[256];
    int r = blockIdx.x;
    const float* a = A + (long)r * cols;
    float s = 0.f;
    for (int c = threadIdx.x; c < cols; c += 256) s += a[c];
    sm[threadIdx.x] = s;
    __syncthreads();
    for (int o = 128; o > 0; o >>= 1) {
        if (threadIdx.x < o) sm[threadIdx.x] += sm[threadIdx.x + o];
        __syncthreads();
    }
    if (threadIdx.x == 0) out[r] = sm[0];
}

// ---------------- column sums (deterministic two-stage) ----------------------
__global__ void colsum_part_kernel(const float* __restrict__ A,
                                   float* __restrict__ part,
                                   int R, int C, int rows_per) {
    int c = blockIdx.x * blockDim.x + threadIdx.x;
    if (c >= C) return;
    int r0 = blockIdx.y * rows_per;
    int r1 = min(r0 + rows_per, R);
    float s = 0.f;
    for (int r = r0; r < r1; r++) s += A[(long)r * C + c];
    part[(long)blockIdx.y * C + c] = s;
}

__global__ void colsum_reduce_kernel(const float* __restrict__ part,
                                     float* __restrict__ out, int C, int P) {
    int c = blockIdx.x * blockDim.x + threadIdx.x;
    if (c >= C) return;
    float s = 0.f;
    for (int p = 0; p < P; p++) s += part[(long)p * C + c];
    out[c] = s;
}

// ---------------- concat: out[r, 0:da] = a[r], out[r, da:da+db] = b[r] ------
__global__ void concat_kernel(const float* __restrict__ a,
                              const float* __restrict__ b,
                              float* __restrict__ out,
                              int n, int da, int db) {
    int dt = da + db;
    long total = (long)n * dt;
    long i = (long)blockIdx.x * blockDim.x + threadIdx.x;
    if (i >= total) return;
    int r = (int)(i / dt), c = (int)(i % dt);
    out[i] = (c < da) ? a[(long)r * da + c] : b[(long)r * db + (c - da)];
}

// ---------------- final small MLP head + softmax ------------------------------
__global__ void head_kernel(const float* __restrict__ v,   // [1024] = v1|v2
                            const float* __restrict__ Wg1, const float* __restrict__ bg1,
                            const float* __restrict__ Wg2, const float* __restrict__ bg2,
                            const float* __restrict__ Wg3, const float* __restrict__ bg3,
                            float* __restrict__ y) {
    __shared__ float sv[2 * HN];
    __shared__ float y1[HN];
    __shared__ float y2[HN];
    __shared__ float logit[3];
    int t = threadIdx.x;  // 512
    sv[t] = v[t];
    sv[t + HN] = v[t + HN];
    __syncthreads();

    {
        float acc = bg1[t];
        const float* w = Wg1 + (long)t * (2 * HN);
        for (int k = 0; k < 2 * HN; k++) acc += sv[k] * w[k];
        y1[t] = fmaxf(acc, 0.f);
    }
    __syncthreads();
    {
        float acc = bg2[t];
        const float* w = Wg2 + (long)t * HN;
        for (int k = 0; k < HN; k++) acc += y1[k] * w[k];
        y2[t] = fmaxf(acc, 0.f);
    }
    __syncthreads();
    if (t < 3) {
        float a = bg3[t];
        const float* w = Wg3 + (long)t * HN;
        for (int k = 0; k < HN; k++) a += y2[k] * w[k];
        logit[t] = a;
    }
    __syncthreads();
    if (t == 0) {
        float m = fmaxf(logit[0], fmaxf(logit[1], logit[2]));
        float e0 = expf(logit[0] - m), e1 = expf(logit[1] - m), e2 = expf(logit[2] - m);
        float s = e0 + e1 + e2;
        y[0] = e0 / s; y[1] = e1 / s; y[2] = e2 / s;
    }
}

// ---------------- host-side gemm dispatch ------------------------------------
static void run_gemm(int amf, int bnf,
                     const float* A, long sAm, long sAk,
                     const float* B, long sBk, long sBn,
                     const float* bias, const float* rowdiv,
                     float* C, int ldc, int M, int N, int K, int relu) {
    dim3 grid((N + 63) / 64, (M + 63) / 64), blk(256);
    if (!amf && !bnf)
        gemm_kernel<false, false><<<grid, blk>>>(A, sAm, sAk, B, sBk, sBn, bias, rowdiv, C, ldc, M, N, K, relu);
    else if (!amf && bnf)
        gemm_kernel<false, true ><<<grid, blk>>>(A, sAm, sAk, B, sBk, sBn, bias, rowdiv, C, ldc, M, N, K, relu);
    else
        gemm_kernel<true,  true ><<<grid, blk>>>(A, sAm, sAk, B, sBk, sBn, bias, rowdiv, C, ldc, M, N, K, relu);
}

extern "C" void kernel_launch(void* const* d_in, const int* in_sizes, int n_in,
                              void* d_out, int out_size) {
    const int*   p_idx = (const int*)  d_in[0];
    const int*   h_idx = (const int*)  d_in[1];
    const float* emb   = (const float*)d_in[2];
    const float* W_a1  = (const float*)d_in[3];
    const float* b_a1  = (const float*)d_in[4];
    const float* W_a2  = (const float*)d_in[5];
    const float* b_a2  = (const float*)d_in[6];
    const float* W_c1  = (const float*)d_in[7];
    const float* b_c1  = (const float*)d_in[8];
    const float* W_c2  = (const float*)d_in[9];
    const float* b_c2  = (const float*)d_in[10];
    const float* W_g1  = (const float*)d_in[11];
    const float* b_g1  = (const float*)d_in[12];
    const float* W_g2  = (const float*)d_in[13];
    const float* b_g2  = (const float*)d_in[14];
    const float* W_g3  = (const float*)d_in[15];
    const float* b_g3  = (const float*)d_in[16];

    float* out = (float*)d_out;
    const long E_OFF    = 0;
    const long BETA_OFF = (long)LPN * LHN;                 // 16777216
    const long ALPHA_OFF= BETA_OFF + (long)LPN * DN;       // 18006016
    const long V1_OFF   = ALPHA_OFF + (long)LHN * DN;      // 19234816
    const long V2_OFF   = V1_OFF + HN;                     // 19235328
    const long Y_OFF    = V2_OFF + HN;                     // 19235840

    float *pemb, *hemb, *t, *fp, *fh, *x, *u, *eik, *ekj, *part;
    cudaGetSymbolAddress((void**)&pemb, g_pemb);
    cudaGetSymbolAddress((void**)&hemb, g_hemb);
    cudaGetSymbolAddress((void**)&t,    g_t);
    cudaGetSymbolAddress((void**)&fp,   g_fp);
    cudaGetSymbolAddress((void**)&fh,   g_fh);
    cudaGetSymbolAddress((void**)&x,    g_x);
    cudaGetSymbolAddress((void**)&u,    g_u);
    cudaGetSymbolAddress((void**)&eik,  g_eik);
    cudaGetSymbolAddress((void**)&ekj,  g_ekj);
    cudaGetSymbolAddress((void**)&part, g_part);

    // 1) gathers
    gather_kernel<<<LPN, 128>>>(emb, p_idx, pemb, DN);
    gather_kernel<<<LHN, 128>>>(emb, h_idx, hemb, DN);

    // 2) attend(p): fp = relu(relu(pemb@Wa1^T+b)@Wa2^T+b)
    run_gemm(0, 0, pemb, DN, 1, W_a1, 1, DN, b_a1, nullptr, t,  HN, LPN, HN, DN, 1);
    run_gemm(0, 0, t,    HN, 1, W_a2, 1, HN, b_a2, nullptr, fp, HN, LPN, HN, HN, 1);
    // 3) attend(h)
    run_gemm(0, 0, hemb, DN, 1, W_a1, 1, DN, b_a1, nullptr, t,  HN, LHN, HN, DN, 1);
    run_gemm(0, 0, t,    HN, 1, W_a2, 1, HN, b_a2, nullptr, fh, HN, LHN, HN, HN, 1);

    // 4) E = fp @ reshape(fh, [H, LH])  -> M[k,j] = fh_flat[k*LH + j]
    run_gemm(0, 1, fp, HN, 1, fh, LHN, 1, nullptr, nullptr,
             out + E_OFF, LHN, LPN, LHN, HN, 0);

    // 5) eik = rowsum(E), ekj = colsum(E)
    rowsum_kernel<<<LPN, 256>>>(out + E_OFF, eik, LHN);
    {
        dim3 g((LHN + 255) / 256, 32);
        colsum_part_kernel<<<g, 256>>>(out + E_OFF, part, LPN, LHN, 128);
        colsum_reduce_kernel<<<(LHN + 255) / 256, 256>>>(part, ekj, LHN, 32);
    }

    // 6) beta = (E @ h_emb) / eik
    run_gemm(0, 1, out + E_OFF, LHN, 1, hemb, DN, 1, nullptr, eik,
             out + BETA_OFF, DN, LPN, DN, LHN, 0);
    // 7) alpha = (E^T @ p_emb) / ekj
    run_gemm(1, 1, out + E_OFF, 1, LHN, pemb, DN, 1, nullptr, ekj,
             out + ALPHA_OFF, DN, LHN, DN, LPN, 0);

    // 8) v1 = colsum(comp([p_emb | beta]))
    {
        long total = (long)LPN * 2 * DN;
        concat_kernel<<<(int)((total + 255) / 256), 256>>>(pemb, out + BETA_OFF, x, LPN, DN, DN);
        run_gemm(0, 0, x, 2 * DN, 1, W_c1, 1, 2 * DN, b_c1, nullptr, t, HN, LPN, HN, 2 * DN, 1);
        run_gemm(0, 0, t, HN, 1,    W_c2, 1, HN,     b_c2, nullptr, u, HN, LPN, HN, HN, 1);
        dim3 g((HN + 255) / 256, 8);
        colsum_part_kernel<<<g, 256>>>(u, part, LPN, HN, 512);
        colsum_reduce_kernel<<<(HN + 255) / 256, 256>>>(part, out + V1_OFF, HN, 8);
    }
    // 9) v2 = colsum(comp([h_emb | alpha]))
    {
        long total = (long)LHN * 2 * DN;
        concat_kernel<<<(int)((total + 255) / 256), 256>>>(hemb, out + ALPHA_OFF, x, LHN, DN, DN);
        run_gemm(0, 0, x, 2 * DN, 1, W_c1, 1, 2 * DN, b_c1, nullptr, t, HN, LHN, HN, 2 * DN, 1);
        run_gemm(0, 0, t, HN, 1,    W_c2, 1, HN,     b_c2, nullptr, u, HN, LHN, HN, HN, 1);
        dim3 g((HN + 255) / 256, 8);
        colsum_part_kernel<<<g, 256>>>(u, part, LHN, HN, 512);
        colsum_reduce_kernel<<<(HN + 255) / 256, 256>>>(part, out + V2_OFF, HN, 8);
    }

    // 10) head: y = softmax(relu(relu([v1|v2]@Wg1^T+b)@Wg2^T+b)@Wg3^T+b)
    head_kernel<<<1, HN>>>(out + V1_OFF, W_g1, b_g1, W_g2, b_g2, W_g3, b_g3, out + Y_OFF);

    (void)in_sizes; (void)n_in; (void)out_size;
}

// round 2
// speedup vs baseline: 1.1675x; 1.1675x over previous
#include <cuda_runtime.h>
#include <cmath>

#define LPN 4096
#define LHN 4096
#define DN  300
#define HN  512

// ---------------- scratch (static device globals; no runtime allocation) ----
__device__ float g_pemb[LPN * DN];
__device__ float g_hemb[LHN * DN];
__device__ float g_t   [LPN * HN];
__device__ float g_fp  [LPN * HN];
__device__ float g_fh  [LHN * HN];
__device__ float g_x   [LPN * 2 * DN];
__device__ float g_u   [LPN * HN];
__device__ float g_eik [LPN];
__device__ float g_ekj [LHN];
__device__ float g_part[32 * 4096];
__device__ float g_split[4 * LPN * DN];   // split-K partials (max 4*4096*300)

// ---------------- gather: out[r,:] = emb[idx[r],:] ---------------------------
__global__ void gather_kernel(const float* __restrict__ emb,
                              const int* __restrict__ idx,
                              float* __restrict__ out, int d) {
    int r = blockIdx.x;
    long src = idx[r];
    const float* s = emb + src * (long)d;
    float* o = out + (long)r * d;
    for (int c = threadIdx.x; c < d; c += blockDim.x) o[c] = s[c];
}

// ---------------- 128x128x16 SGEMM, 8x8 microtile, fully vectorized ---------
// C[m,n] = epi( sum_{k in [kbeg,kend)} A[m*sAm + k*sAk] * B[k*sBk + n*sBn] )
// AKF: A k-contiguous (sAk==1); else A m-contiguous (sAm==1).
// BNF: B n-contiguous (sBn==1); else B k-contiguous (sBk==1).
// Requires: all vectorized dims (K, N, leading strides) multiples of 4.
// blockIdx.z = split-K slice; C advanced by sliceStride per slice.
template <bool AKF, bool BNF>
__launch_bounds__(256, 2)
__global__ void gemm128(const float* __restrict__ A, long sAm, long sAk,
                        const float* __restrict__ B, long sBk, long sBn,
                        const float* __restrict__ bias,
                        const float* __restrict__ rowdiv,
                        float* __restrict__ C, long ldc, long sliceStride,
                        int M, int N, int K, int kchunk, int relu) {
    __shared__ float As[16][132];
    __shared__ float Bs[16][132];

    int tid = threadIdx.x;
    int m0 = blockIdx.y * 128;
    int n0 = blockIdx.x * 128;
    int kbeg = blockIdx.z * kchunk;
    int kend = min(K, kbeg + kchunk);
    C += (long)blockIdx.z * sliceStride;

    float acc[8][8];
    #pragma unroll
    for (int i = 0; i < 8; i++)
        #pragma unroll
        for (int j = 0; j < 8; j++) acc[i][j] = 0.f;

    const int ty = tid >> 4, tx = tid & 15;

    for (int k0 = kbeg; k0 < kend; k0 += 16) {
        // ---- A tile: 128(m) x 16(k) -> As[k][m] ----
        if (AKF) {
            int ar = tid >> 2, ac = (tid & 3) << 2;
            #pragma unroll
            for (int r = 0; r < 2; r++) {
                int mm = ar + r * 64;
                int m = m0 + mm;
                int k = k0 + ac;
                float4 v = make_float4(0.f, 0.f, 0.f, 0.f);
                if (k < kend && m < M)
                    v = *(const float4*)(A + (long)m * sAm + k);
                As[ac + 0][mm] = v.x; As[ac + 1][mm] = v.y;
                As[ac + 2][mm] = v.z; As[ac + 3][mm] = v.w;
            }
        } else {
            int ak = tid >> 5, am = (tid & 31) << 2;
            #pragma unroll
            for (int r = 0; r < 2; r++) {
                int kk = ak + r * 8;
                int k = k0 + kk;
                int m = m0 + am;
                float4 v = make_float4(0.f, 0.f, 0.f, 0.f);
                if (k < kend && m < M)
                    v = *(const float4*)(A + (long)k * sAk + m);
                *(float4*)&As[kk][am] = v;
            }
        }
        // ---- B tile: 16(k) x 128(n) -> Bs[k][n] ----
        if (BNF) {
            int bk = tid >> 5, bn = (tid & 31) << 2;
            #pragma unroll
            for (int r = 0; r < 2; r++) {
                int kk = bk + r * 8;
                int k = k0 + kk;
                int n = n0 + bn;
                float4 v = make_float4(0.f, 0.f, 0.f, 0.f);
                if (k < kend && n < N)
                    v = *(const float4*)(B + (long)k * sBk + n);
                *(float4*)&Bs[kk][bn] = v;
            }
        } else {
            int bn = tid >> 2, bc = (tid & 3) << 2;
            #pragma unroll
            for (int r = 0; r < 2; r++) {
                int nn = bn + r * 64;
                int n = n0 + nn;
                int k = k0 + bc;
                float4 v = make_float4(0.f, 0.f, 0.f, 0.f);
                if (k < kend && n < N)
                    v = *(const float4*)(B + (long)n * sBn + k);
                Bs[bc + 0][nn] = v.x; Bs[bc + 1][nn] = v.y;
                Bs[bc + 2][nn] = v.z; Bs[bc + 3][nn] = v.w;
            }
        }
        __syncthreads();

        #pragma unroll
        for (int kk = 0; kk < 16; kk++) {
            float a[8], b[8];
            *(float4*)&a[0] = *(const float4*)&As[kk][ty * 8];
            *(float4*)&a[4] = *(const float4*)&As[kk][ty * 8 + 4];
            *(float4*)&b[0] = *(const float4*)&Bs[kk][tx * 8];
            *(float4*)&b[4] = *(const float4*)&Bs[kk][tx * 8 + 4];
            #pragma unroll
            for (int i = 0; i < 8; i++)
                #pragma unroll
                for (int j = 0; j < 8; j++)
                    acc[i][j] = fmaf(a[i], b[j], acc[i][j]);
        }
        __syncthreads();
    }

    // ---- epilogue (float4 stores; N, ldc multiples of 4) ----
    #pragma unroll
    for (int i = 0; i < 8; i++) {
        int m = m0 + ty * 8 + i;
        if (m >= M) continue;
        float rd = rowdiv ? rowdiv[m] : 1.f;
        #pragma unroll
        for (int j4 = 0; j4 < 2; j4++) {
            int n = n0 + tx * 8 + j4 * 4;
            if (n >= N) continue;
            float4 v;
            v.x = acc[i][j4 * 4 + 0]; v.y = acc[i][j4 * 4 + 1];
            v.z = acc[i][j4 * 4 + 2]; v.w = acc[i][j4 * 4 + 3];
            if (bias) {
                v.x += bias[n + 0]; v.y += bias[n + 1];
                v.z += bias[n + 2]; v.w += bias[n + 3];
            }
            if (relu) {
                v.x = fmaxf(v.x, 0.f); v.y = fmaxf(v.y, 0.f);
                v.z = fmaxf(v.z, 0.f); v.w = fmaxf(v.w, 0.f);
            }
            if (rowdiv) { v.x /= rd; v.y /= rd; v.z /= rd; v.w /= rd; }
            *(float4*)(C + (long)m * ldc + n) = v;
        }
    }
}

// ---------------- split-K reduce with per-row divide --------------------------
__global__ void splitk_reduce_kernel(const float* __restrict__ part,
                                     const float* __restrict__ rowdiv,
                                     float* __restrict__ C, long ldc,
                                     int M, int N, int S) {
    long i = (long)blockIdx.x * blockDim.x + threadIdx.x;
    long total = (long)M * N;
    if (i >= total) return;
    int m = (int)(i / N), n = (int)(i % N);
    float s = 0.f;
    for (int p = 0; p < S; p++) s += part[(long)p * total + i];
    C[(long)m * ldc + n] = s / rowdiv[m];
}

// ---------------- row sums: out[r] = sum_c A[r,c] ---------------------------
__global__ void rowsum_kernel(const float* __restrict__ A,
                              float* __restrict__ out, int cols) {
    __shared__ float sm[256];
    int r = blockIdx.x;
    const float* a = A + (long)r * cols;
    float s = 0.f;
    for (int c = threadIdx.x; c < cols; c += 256) s += a[c];
    sm[threadIdx.x] = s;
    __syncthreads();
    for (int o = 128; o > 0; o >>= 1) {
        if (threadIdx.x < o) sm[threadIdx.x] += sm[threadIdx.x + o];
        __syncthreads();
    }
    if (threadIdx.x == 0) out[r] = sm[0];
}

// ---------------- column sums (deterministic two-stage) ----------------------
__global__ void colsum_part_kernel(const float* __restrict__ A,
                                   float* __restrict__ part,
                                   int R, int C, int rows_per) {
    int c = blockIdx.x * blockDim.x + threadIdx.x;
    if (c >= C) return;
    int r0 = blockIdx.y * rows_per;
    int r1 = min(r0 + rows_per, R);
    float s = 0.f;
    for (int r = r0; r < r1; r++) s += A[(long)r * C + c];
    part[(long)blockIdx.y * C + c] = s;
}

__global__ void colsum_reduce_kernel(const float* __restrict__ part,
                                     float* __restrict__ out, int C, int P) {
    int c = blockIdx.x * blockDim.x + threadIdx.x;
    if (c >= C) return;
    float s = 0.f;
    for (int p = 0; p < P; p++) s += part[(long)p * C + c];
    out[c] = s;
}

// ---------------- concat: out[r, 0:da] = a[r], out[r, da:da+db] = b[r] ------
__global__ void concat_kernel(const float* __restrict__ a,
                              const float* __restrict__ b,
                              float* __restrict__ out,
                              int n, int da, int db) {
    int dt = da + db;
    long total = (long)n * dt;
    long i = (long)blockIdx.x * blockDim.x + threadIdx.x;
    if (i >= total) return;
    int r = (int)(i / dt), c = (int)(i % dt);
    out[i] = (c < da) ? a[(long)r * da + c] : b[(long)r * db + (c - da)];
}

// ---------------- final small MLP head + softmax ------------------------------
__global__ void head_kernel(const float* __restrict__ v,   // [1024] = v1|v2
                            const float* __restrict__ Wg1, const float* __restrict__ bg1,
                            const float* __restrict__ Wg2, const float* __restrict__ bg2,
                            const float* __restrict__ Wg3, const float* __restrict__ bg3,
                            float* __restrict__ y) {
    __shared__ float sv[2 * HN];
    __shared__ float y1[HN];
    __shared__ float y2[HN];
    __shared__ float logit[3];
    int t = threadIdx.x;  // 512
    sv[t] = v[t];
    sv[t + HN] = v[t + HN];
    __syncthreads();
    {
        float acc = bg1[t];
        const float* w = Wg1 + (long)t * (2 * HN);
        for (int k = 0; k < 2 * HN; k++) acc += sv[k] * w[k];
        y1[t] = fmaxf(acc, 0.f);
    }
    __syncthreads();
    {
        float acc = bg2[t];
        const float* w = Wg2 + (long)t * HN;
        for (int k = 0; k < HN; k++) acc += y1[k] * w[k];
        y2[t] = fmaxf(acc, 0.f);
    }
    __syncthreads();
    if (t < 3) {
        float a = bg3[t];
        const float* w = Wg3 + (long)t * HN;
        for (int k = 0; k < HN; k++) a += y2[k] * w[k];
        logit[t] = a;
    }
    __syncthreads();
    if (t == 0) {
        float m = fmaxf(logit[0], fmaxf(logit[1], logit[2]));
        float e0 = expf(logit[0] - m), e1 = expf(logit[1] - m), e2 = expf(logit[2] - m);
        float s = e0 + e1 + e2;
        y[0] = e0 / s; y[1] = e1 / s; y[2] = e2 / s;
    }
}

// ---------------- host-side gemm dispatch ------------------------------------
static void launch_gemm(int akf, int bnf,
                        const float* A, long sAm, long sAk,
                        const float* B, long sBk, long sBn,
                        const float* bias, const float* rowdiv,
                        float* C, long ldc, long sliceStride,
                        int M, int N, int K, int splits, int relu) {
    int kchunk = (K + splits - 1) / splits;
    kchunk = ((kchunk + 15) / 16) * 16;
    dim3 grid((N + 127) / 128, (M + 127) / 128, splits);
    if (akf && bnf)
        gemm128<true, true ><<<grid, 256>>>(A, sAm, sAk, B, sBk, sBn, bias, rowdiv, C, ldc, sliceStride, M, N, K, kchunk, relu);
    else if (akf)
        gemm128<true, false><<<grid, 256>>>(A, sAm, sAk, B, sBk, sBn, bias, rowdiv, C, ldc, sliceStride, M, N, K, kchunk, relu);
    else if (bnf)
        gemm128<false, true><<<grid, 256>>>(A, sAm, sAk, B, sBk, sBn, bias, rowdiv, C, ldc, sliceStride, M, N, K, kchunk, relu);
    else
        gemm128<false, false><<<grid, 256>>>(A, sAm, sAk, B, sBk, sBn, bias, rowdiv, C, ldc, sliceStride, M, N, K, kchunk, relu);
}

extern "C" void kernel_launch(void* const* d_in, const int* in_sizes, int n_in,
                              void* d_out, int out_size) {
    const int*   p_idx = (const int*)  d_in[0];
    const int*   h_idx = (const int*)  d_in[1];
    const float* emb   = (const float*)d_in[2];
    const float* W_a1  = (const float*)d_in[3];
    const float* b_a1  = (const float*)d_in[4];
    const float* W_a2  = (const float*)d_in[5];
    const float* b_a2  = (const float*)d_in[6];
    const float* W_c1  = (const float*)d_in[7];
    const float* b_c1  = (const float*)d_in[8];
    const float* W_c2  = (const float*)d_in[9];
    const float* b_c2  = (const float*)d_in[10];
    const float* W_g1  = (const float*)d_in[11];
    const float* b_g1  = (const float*)d_in[12];
    const float* W_g2  = (const float*)d_in[13];
    const float* b_g2  = (const float*)d_in[14];
    const float* W_g3  = (const float*)d_in[15];
    const float* b_g3  = (const float*)d_in[16];

    float* out = (float*)d_out;
    const long E_OFF    = 0;
    const long BETA_OFF = (long)LPN * LHN;
    const long ALPHA_OFF= BETA_OFF + (long)LPN * DN;
    const long V1_OFF   = ALPHA_OFF + (long)LHN * DN;
    const long V2_OFF   = V1_OFF + HN;
    const long Y_OFF    = V2_OFF + HN;

    float *pemb, *hemb, *t, *fp, *fh, *x, *u, *eik, *ekj, *part, *split;
    cudaGetSymbolAddress((void**)&pemb,  g_pemb);
    cudaGetSymbolAddress((void**)&hemb,  g_hemb);
    cudaGetSymbolAddress((void**)&t,     g_t);
    cudaGetSymbolAddress((void**)&fp,    g_fp);
    cudaGetSymbolAddress((void**)&fh,    g_fh);
    cudaGetSymbolAddress((void**)&x,     g_x);
    cudaGetSymbolAddress((void**)&u,     g_u);
    cudaGetSymbolAddress((void**)&eik,   g_eik);
    cudaGetSymbolAddress((void**)&ekj,   g_ekj);
    cudaGetSymbolAddress((void**)&part,  g_part);
    cudaGetSymbolAddress((void**)&split, g_split);

    // 1) gathers
    gather_kernel<<<LPN, 128>>>(emb, p_idx, pemb, DN);
    gather_kernel<<<LHN, 128>>>(emb, h_idx, hemb, DN);

    // 2) attend(p): fp = relu(relu(pemb@Wa1^T+b)@Wa2^T+b)
    launch_gemm(1, 0, pemb, DN, 1, W_a1, 1, DN, b_a1, nullptr, t,  HN, 0, LPN, HN, DN, 1, 1);
    launch_gemm(1, 0, t,    HN, 1, W_a2, 1, HN, b_a2, nullptr, fp, HN, 0, LPN, HN, HN, 1, 1);
    // 3) attend(h)
    launch_gemm(1, 0, hemb, DN, 1, W_a1, 1, DN, b_a1, nullptr, t,  HN, 0, LHN, HN, DN, 1, 1);
    launch_gemm(1, 0, t,    HN, 1, W_a2, 1, HN, b_a2, nullptr, fh, HN, 0, LHN, HN, HN, 1, 1);

    // 4) E = fp @ reshape(fh, [H, LH])  -> B[k,j] = fh_flat[k*LH + j]
    launch_gemm(1, 1, fp, HN, 1, fh, LHN, 1, nullptr, nullptr,
                out + E_OFF, LHN, 0, LPN, LHN, HN, 1, 0);

    // 5) eik = rowsum(E), ekj = colsum(E)
    rowsum_kernel<<<LPN, 256>>>(out + E_OFF, eik, LHN);
    {
        dim3 g((LHN + 255) / 256, 32);
        colsum_part_kernel<<<g, 256>>>(out + E_OFF, part, LPN, LHN, 128);
        colsum_reduce_kernel<<<(LHN + 255) / 256, 256>>>(part, ekj, LHN, 32);
    }

    // 6) beta = (E @ h_emb) / eik   -- split-K x4
    launch_gemm(1, 1, out + E_OFF, LHN, 1, hemb, DN, 1, nullptr, nullptr,
                split, DN, (long)LPN * DN, LPN, DN, LHN, 4, 0);
    {
        long total = (long)LPN * DN;
        splitk_reduce_kernel<<<(int)((total + 255) / 256), 256>>>(
            split, eik, out + BETA_OFF, DN, LPN, DN, 4);
    }
    // 7) alpha = (E^T @ p_emb) / ekj   -- split-K x4 (A m-contiguous)
    launch_gemm(0, 1, out + E_OFF, 1, LHN, pemb, DN, 1, nullptr, nullptr,
                split, DN, (long)LHN * DN, LHN, DN, LPN, 4, 0);
    {
        long total = (long)LHN * DN;
        splitk_reduce_kernel<<<(int)((total + 255) / 256), 256>>>(
            split, ekj, out + ALPHA_OFF, DN, LHN, DN, 4);
    }

    // 8) v1 = colsum(comp([p_emb | beta]))
    {
        long total = (long)LPN * 2 * DN;
        concat_kernel<<<(int)((total + 255) / 256), 256>>>(pemb, out + BETA_OFF, x, LPN, DN, DN);
        launch_gemm(1, 0, x, 2 * DN, 1, W_c1, 1, 2 * DN, b_c1, nullptr, t, HN, 0, LPN, HN, 2 * DN, 1, 1);
        launch_gemm(1, 0, t, HN, 1,    W_c2, 1, HN,     b_c2, nullptr, u, HN, 0, LPN, HN, HN, 1, 1);
        dim3 g((HN + 255) / 256, 8);
        colsum_part_kernel<<<g, 256>>>(u, part, LPN, HN, 512);
        colsum_reduce_kernel<<<(HN + 255) / 256, 256>>>(part, out + V1_OFF, HN, 8);
    }
    // 9) v2 = colsum(comp([h_emb | alpha]))
    {
        long total = (long)LHN * 2 * DN;
        concat_kernel<<<(int)((total + 255) / 256), 256>>>(hemb, out + ALPHA_OFF, x, LHN, DN, DN);
        launch_gemm(1, 0, x, 2 * DN, 1, W_c1, 1, 2 * DN, b_c1, nullptr, t, HN, 0, LHN, HN, 2 * DN, 1, 1);
        launch_gemm(1, 0, t, HN, 1,    W_c2, 1, HN,     b_c2, nullptr, u, HN, 0, LHN, HN, HN, 1, 1);
        dim3 g((HN + 255) / 256, 8);
        colsum_part_kernel<<<g, 256>>>(u, part, LHN, HN, 512);
        colsum_reduce_kernel<<<(HN + 255) / 256, 256>>>(part, out + V2_OFF, HN, 8);
    }

    // 10) head
    head_kernel<<<1, HN>>>(out + V1_OFF, W_g1, b_g1, W_g2, b_g2, W_g3, b_g3, out + Y_OFF);

    (void)in_sizes; (void)n_in; (void)out_size;
}